// round 8
// baseline (speedup 1.0000x reference)
#include <cuda_runtime.h>
#include <math.h>
#include <stdint.h>

#define NB    16
#define H8    44
#define W8    144
#define HWLO  (H8 * W8)        // 6336
#define NPIX  (NB * HWLO)      // 101376
#define HOUT  (H8 * 8)         // 352
#define WOUT  (W8 * 8)         // 1152
#define P     128              // pixels per tile
#define NTILES (NPIX / P)      // 792
#define NCTA  296              // 2 per SM, single wave
#define NTHR  256
#define CHK   32               // channels per x chunk
#define NCHK  4
#define PI_F  3.1415926535f
#define MAX_DEPTH 81.0f

typedef unsigned long long u64;

// ---- dynamic smem layout (float offsets) ----
#define OFF_XB    0            // [2][32][128] = 8192 f (double-buffered x chunks)
#define OFF_A2S   0            // [32][128] 4096 f — aliases XB (x dead after layer 1)
#define OFF_A1S   8192         // [64][128] 8192 f
#define OFF_PLN   8192         // [4][128]  — aliases A1S (a1 dead after layer 2)
#define OFF_WT0   16384        // [128][64] 8192 f
#define OFF_WT1   24576        // [64][32]  2048 f
#define OFF_WT2   26624        // [32][16]  512 f
#define OFF_WT3   27136        // [16][8]   128 f
#define OFF_WT4   27264        // [8][4]    32 f
#define OFF_WC    27296        // 16 f
#define OFF_B0    27312        // 64
#define OFF_B1    27376        // 32
#define OFF_B2    27408        // 16
#define OFF_B3    27424        // 8
#define OFF_B4    27432        // 4
#define OFF_BC    27436        // 4
#define SMEM_FLOATS 27440
#define SMEM_BYTES  (SMEM_FLOATS * 4)   // 109760 B -> 2 CTAs/SM

// ---------------- packed f32x2 helpers (sm_103a) -------------------------------
__device__ __forceinline__ u64 pack2(float lo, float hi) {
    u64 r; asm("mov.b64 %0, {%1, %2};" : "=l"(r) : "f"(lo), "f"(hi)); return r;
}
__device__ __forceinline__ void unpack2(u64 v, float& lo, float& hi) {
    asm("mov.b64 {%0, %1}, %2;" : "=f"(lo), "=f"(hi) : "l"(v));
}
__device__ __forceinline__ u64 fma2(u64 a, u64 b, u64 c) {
    u64 d; asm("fma.rn.f32x2 %0, %1, %2, %3;" : "=l"(d) : "l"(a), "l"(b), "l"(c));
    return d;
}

// branch-free ELU: max(v,0) + (exp(min(v,0)) - 1)
__device__ __forceinline__ float eluf(float v) {
    return fmaxf(v, 0.0f) + (__expf(fminf(v, 0.0f)) - 1.0f);
}
__device__ __forceinline__ float sigmoidf_fast(float v) {
    return __fdividef(1.0f, 1.0f + __expf(-v));
}

// ---------------- cp.async helpers ---------------------------------------------
__device__ __forceinline__ void cp_async16(uint32_t dst, const void* src) {
    asm volatile("cp.async.cg.shared.global [%0], [%1], 16;" :: "r"(dst), "l"(src));
}
#define CP_COMMIT() asm volatile("cp.async.commit_group;" ::: "memory")
#define CP_WAIT(N)  asm volatile("cp.async.wait_group %0;" :: "n"(N) : "memory")

// stage one 32-channel x chunk into xb (1024 float4 = 4 per thread)
__device__ __forceinline__ void stage_chunk(float* xb, const float* __restrict__ x,
                                            int p0, int k, int t) {
    const uint32_t dst0 = (uint32_t)__cvta_generic_to_shared(xb);
#pragma unroll
    for (int j = 0; j < 4; j++) {
        const int i  = t + j * 256;     // 0..1023
        const int cl = i >> 5;          // local channel 0..31
        const int g  = i & 31;          // 4-pixel group
        const int p  = p0 + 4 * g;
        const int bb = p / HWLO;
        const int hw = p - bb * HWLO;
        const float* src = x + ((size_t)(bb * 128 + k * CHK + cl)) * HWLO + hw;
        cp_async16(dst0 + (uint32_t)(cl * 128 + 4 * g) * 4u, src);
    }
    CP_COMMIT();
}

// ---------------------------------- kernel ------------------------------------
__global__ __launch_bounds__(NTHR, 2) void lpg_fused_kernel(
    const float* __restrict__ x,
    const float* __restrict__ w0, const float* __restrict__ b0,
    const float* __restrict__ w1, const float* __restrict__ b1,
    const float* __restrict__ w2, const float* __restrict__ b2,
    const float* __restrict__ w3, const float* __restrict__ b3,
    const float* __restrict__ w4, const float* __restrict__ b4,
    const float* __restrict__ wc, const float* __restrict__ bc,
    float* __restrict__ out)
{
    extern __shared__ float sm[];
    float* xb0 = sm + OFF_XB;
    float* xb1 = sm + OFF_XB + CHK * 128;
    float* a2s = sm + OFF_A2S;
    float* a1s = sm + OFF_A1S;
    float* pln = sm + OFF_PLN;
    float* wT0 = sm + OFF_WT0;
    float* wT1 = sm + OFF_WT1;
    float* wT2 = sm + OFF_WT2;
    float* wT3 = sm + OFF_WT3;
    float* wT4 = sm + OFF_WT4;
    float* sWc = sm + OFF_WC;
    float* sB0 = sm + OFF_B0;
    float* sB1 = sm + OFF_B1;
    float* sB2 = sm + OFF_B2;
    float* sB3 = sm + OFF_B3;
    float* sB4 = sm + OFF_B4;
    float* sBc = sm + OFF_BC;

    const int t = threadIdx.x;

    // ---- stage all weights once (persistent CTA) --------------------------------
    for (int j = t; j < 128 * 64; j += NTHR) { int o = j >> 7, c = j & 127; wT0[c * 64 + o] = w0[j]; }
    for (int j = t; j < 64 * 32;  j += NTHR) { int o = j >> 6, c = j & 63;  wT1[c * 32 + o] = w1[j]; }
    for (int j = t; j < 32 * 16;  j += NTHR) { int o = j >> 5, c = j & 31;  wT2[c * 16 + o] = w2[j]; }
    if (t < 128) { int o = t >> 4, c = t & 15; wT3[c * 8 + o] = w3[t]; }
    if (t < 32)  { int o = t >> 3, c = t & 7;  wT4[c * 4 + o] = w4[t]; }
    if (t < 12)  { int o = t >> 2, c = t & 3;  sWc[c * 3 + o] = wc[t]; }
    if (t < 64) sB0[t] = b0[t];
    if (t < 32) sB1[t] = b1[t];
    if (t < 16) sB2[t] = b2[t];
    if (t < 8)  sB3[t] = b3[t];
    if (t < 4)  sB4[t] = b4[t];
    if (t < 3)  sBc[t] = bc[t];
    __syncthreads();

    const int pg = t & 31;     // 4-pixel group 0..31
    const int og = t >> 5;     // out group 0..7 (warp-uniform)
    const int pl = 4 * pg;
    const float* __restrict__ wrow0 = wT0 + og * 8;
    const float* __restrict__ wrow1 = wT1 + og * 4;

    for (int tile = blockIdx.x; tile < NTILES; tile += NCTA) {
        const int p0 = tile * P;

        // prologue: chunk 0 in flight
        stage_chunk(xb0, x, p0, 0, t);

        // ---- layer 1: 128 -> 64, frag = 4 pix x 8 outs, x double-buffered -------
        const u64* b0p = (const u64*)sB0;
        u64 acc[4][4];
#pragma unroll
        for (int j = 0; j < 4; j++) {
            const u64 bv = b0p[og * 4 + j];
            acc[0][j] = bv; acc[1][j] = bv; acc[2][j] = bv; acc[3][j] = bv;
        }

#pragma unroll
        for (int k = 0; k < NCHK; k++) {
            if (k + 1 < NCHK) {
                stage_chunk((k & 1) ? xb0 : xb1, x, p0, k + 1, t);
                CP_WAIT(1);                  // chunk k complete, k+1 pending
            } else {
                CP_WAIT(0);
            }
            __syncthreads();                 // chunk k visible to all threads
            const float* __restrict__ xc = (k & 1) ? xb1 : xb0;
#pragma unroll 4
            for (int c = 0; c < CHK; c++) {
                const int cg = k * CHK + c;
                const float4 xv = *(const float4*)(xc + c * 128 + pl);
                const ulonglong2 wa = *(const ulonglong2*)(wrow0 + cg * 64);
                const ulonglong2 wb = *(const ulonglong2*)(wrow0 + cg * 64 + 4);
                const u64 x0 = pack2(xv.x, xv.x), x1 = pack2(xv.y, xv.y);
                const u64 x2 = pack2(xv.z, xv.z), x3 = pack2(xv.w, xv.w);
                acc[0][0] = fma2(wa.x, x0, acc[0][0]); acc[0][1] = fma2(wa.y, x0, acc[0][1]);
                acc[0][2] = fma2(wb.x, x0, acc[0][2]); acc[0][3] = fma2(wb.y, x0, acc[0][3]);
                acc[1][0] = fma2(wa.x, x1, acc[1][0]); acc[1][1] = fma2(wa.y, x1, acc[1][1]);
                acc[1][2] = fma2(wb.x, x1, acc[1][2]); acc[1][3] = fma2(wb.y, x1, acc[1][3]);
                acc[2][0] = fma2(wa.x, x2, acc[2][0]); acc[2][1] = fma2(wa.y, x2, acc[2][1]);
                acc[2][2] = fma2(wb.x, x2, acc[2][2]); acc[2][3] = fma2(wb.y, x2, acc[2][3]);
                acc[3][0] = fma2(wa.x, x3, acc[3][0]); acc[3][1] = fma2(wa.y, x3, acc[3][1]);
                acc[3][2] = fma2(wb.x, x3, acc[3][2]); acc[3][3] = fma2(wb.y, x3, acc[3][3]);
            }
            __syncthreads();                 // all reads of buf done before reuse
        }

        // ELU + scatter a1 (STS.128 per out channel)
#pragma unroll
        for (int j = 0; j < 4; j++) {
            float l0, h0, l1, h1, l2, h2, l3, h3;
            unpack2(acc[0][j], l0, h0); unpack2(acc[1][j], l1, h1);
            unpack2(acc[2][j], l2, h2); unpack2(acc[3][j], l3, h3);
            const int o0 = og * 8 + 2 * j;
            *(float4*)(a1s + o0 * 128 + pl)       = make_float4(eluf(l0), eluf(l1), eluf(l2), eluf(l3));
            *(float4*)(a1s + (o0 + 1) * 128 + pl) = make_float4(eluf(h0), eluf(h1), eluf(h2), eluf(h3));
        }
        __syncthreads();

        // ---- layer 2: 64 -> 32, frag = 4 pix x 4 outs ----------------------------
        {
            const u64* b1p = (const u64*)sB1;
            u64 a2[4][2];
#pragma unroll
            for (int j = 0; j < 2; j++) {
                const u64 bv = b1p[og * 2 + j];
                a2[0][j] = bv; a2[1][j] = bv; a2[2][j] = bv; a2[3][j] = bv;
            }
#pragma unroll 4
            for (int c = 0; c < 64; c++) {
                const float4 av = *(const float4*)(a1s + c * 128 + pl);
                const ulonglong2 w = *(const ulonglong2*)(wrow1 + c * 32);
                const u64 x0 = pack2(av.x, av.x), x1 = pack2(av.y, av.y);
                const u64 x2 = pack2(av.z, av.z), x3 = pack2(av.w, av.w);
                a2[0][0] = fma2(w.x, x0, a2[0][0]); a2[0][1] = fma2(w.y, x0, a2[0][1]);
                a2[1][0] = fma2(w.x, x1, a2[1][0]); a2[1][1] = fma2(w.y, x1, a2[1][1]);
                a2[2][0] = fma2(w.x, x2, a2[2][0]); a2[2][1] = fma2(w.y, x2, a2[2][1]);
                a2[3][0] = fma2(w.x, x3, a2[3][0]); a2[3][1] = fma2(w.y, x3, a2[3][1]);
            }
            // a2s aliases the x buffers — x reads finished (post-barrier above)
#pragma unroll
            for (int j = 0; j < 2; j++) {
                float l0, h0, l1, h1, l2, h2, l3, h3;
                unpack2(a2[0][j], l0, h0); unpack2(a2[1][j], l1, h1);
                unpack2(a2[2][j], l2, h2); unpack2(a2[3][j], l3, h3);
                const int o0 = og * 4 + 2 * j;
                *(float4*)(a2s + o0 * 128 + pl)       = make_float4(eluf(l0), eluf(l1), eluf(l2), eluf(l3));
                *(float4*)(a2s + (o0 + 1) * 128 + pl) = make_float4(eluf(h0), eluf(h1), eluf(h2), eluf(h3));
            }
        }
        __syncthreads();

        // ---- tail: 1 thread per pixel (t < 128), writes plane params -------------
        if (t < P) {
            float a3[16];
            {
                const u64* b2p = (const u64*)sB2;
                u64 acc3[8];
#pragma unroll
                for (int j = 0; j < 8; j++) acc3[j] = b2p[j];
#pragma unroll 4
                for (int c = 0; c < 32; c++) {
                    const float v = a2s[c * 128 + t];
                    const u64 xx = pack2(v, v);
                    const ulonglong2 wa = *(const ulonglong2*)(wT2 + c * 16);
                    const ulonglong2 wb = *(const ulonglong2*)(wT2 + c * 16 + 4);
                    const ulonglong2 wc2 = *(const ulonglong2*)(wT2 + c * 16 + 8);
                    const ulonglong2 wd = *(const ulonglong2*)(wT2 + c * 16 + 12);
                    acc3[0] = fma2(wa.x, xx, acc3[0]);  acc3[1] = fma2(wa.y, xx, acc3[1]);
                    acc3[2] = fma2(wb.x, xx, acc3[2]);  acc3[3] = fma2(wb.y, xx, acc3[3]);
                    acc3[4] = fma2(wc2.x, xx, acc3[4]); acc3[5] = fma2(wc2.y, xx, acc3[5]);
                    acc3[6] = fma2(wd.x, xx, acc3[6]);  acc3[7] = fma2(wd.y, xx, acc3[7]);
                }
#pragma unroll
                for (int j = 0; j < 8; j++) {
                    float lo, hi; unpack2(acc3[j], lo, hi);
                    a3[2 * j] = eluf(lo); a3[2 * j + 1] = eluf(hi);
                }
            }
            float a4[8];
            {
                const u64* b3p = (const u64*)sB3;
                u64 acc4[4];
#pragma unroll
                for (int j = 0; j < 4; j++) acc4[j] = b3p[j];
#pragma unroll
                for (int c = 0; c < 16; c++) {
                    const u64 xx = pack2(a3[c], a3[c]);
                    const ulonglong2 wa = *(const ulonglong2*)(wT3 + c * 8);
                    const ulonglong2 wb = *(const ulonglong2*)(wT3 + c * 8 + 4);
                    acc4[0] = fma2(wa.x, xx, acc4[0]); acc4[1] = fma2(wa.y, xx, acc4[1]);
                    acc4[2] = fma2(wb.x, xx, acc4[2]); acc4[3] = fma2(wb.y, xx, acc4[3]);
                }
#pragma unroll
                for (int j = 0; j < 4; j++) {
                    float lo, hi; unpack2(acc4[j], lo, hi);
                    a4[2 * j] = eluf(lo); a4[2 * j + 1] = eluf(hi);
                }
            }
            float a5[4];
            {
                const u64* b4p = (const u64*)sB4;
                u64 acc5[2];
                acc5[0] = b4p[0]; acc5[1] = b4p[1];
#pragma unroll
                for (int c = 0; c < 8; c++) {
                    const u64 xx = pack2(a4[c], a4[c]);
                    const ulonglong2 w = *(const ulonglong2*)(wT4 + c * 4);
                    acc5[0] = fma2(w.x, xx, acc5[0]); acc5[1] = fma2(w.y, xx, acc5[1]);
                }
                unpack2(acc5[0], a5[0], a5[1]); unpack2(acc5[1], a5[2], a5[3]);
            }
            float y[3];
#pragma unroll
            for (int o = 0; o < 3; o++) {
                float s = sBc[o];
#pragma unroll
                for (int c = 0; c < 4; c++) s += sWc[c * 3 + o] * a5[c];
                y[o] = s;
            }
            const float theta = sigmoidf_fast(y[0]) * (PI_F / 6.0f);
            const float phi   = sigmoidf_fast(y[1]) * (PI_F * 2.0f);
            const float dist  = sigmoidf_fast(y[2]) * MAX_DEPTH;
            const float st = __sinf(theta), ct = __cosf(theta);
            const float sp = __sinf(phi),   cp = __cosf(phi);
            float nx = st * cp, ny = st * sp, nz = ct;
            const float inv = rsqrtf(nx * nx + ny * ny + nz * nz);
            // pln aliases a1s — all a1 reads finished (layer-2 + barrier)
            pln[0 * 128 + t] = nx * inv;
            pln[1 * 128 + t] = ny * inv;
            pln[2 * 128 + t] = nz * inv;
            pln[3 * 128 + t] = dist;
        }
        __syncthreads();

        // ---- epilogue: 2 threads per pixel, 4 rows each ---------------------------
        {
            const int px   = t >> 1;
            const int half = t & 1;
            const float nx   = pln[0 * 128 + px];
            const float ny   = pln[1 * 128 + px];
            const float nz   = pln[2 * 128 + px];
            const float dist = pln[3 * 128 + px];

            const int p  = p0 + px;
            const int bb = p / HWLO;
            const int hw = p - bb * HWLO;
            const int h  = hw / W8;
            const int w  = hw - h * W8;
            float* __restrict__ op = out + ((size_t)bb * HOUT + (size_t)h * 8) * WOUT + (size_t)w * 8;

#pragma unroll
            for (int r = 0; r < 4; r++) {
                const int i = half * 4 + r;
                const float vterm = ny * ((float)i - 3.5f) * 0.125f + nz;
                float row[8];
#pragma unroll
                for (int j = 0; j < 8; j++) {
                    const float u = ((float)j - 3.5f) * 0.125f;
                    row[j] = __fdividef(dist, nx * u + vterm);
                }
                float4* o4 = (float4*)(op + (size_t)i * WOUT);
                o4[0] = make_float4(row[0], row[1], row[2], row[3]);
                o4[1] = make_float4(row[4], row[5], row[6], row[7]);
            }
        }
        __syncthreads();   // pln/xb reuse next tile
    }
}

extern "C" void kernel_launch(void* const* d_in, const int* in_sizes, int n_in,
                              void* d_out, int out_size) {
    const float* x  = (const float*)d_in[0];
    const float* w0 = (const float*)d_in[1];
    const float* b0 = (const float*)d_in[2];
    const float* w1 = (const float*)d_in[3];
    const float* b1 = (const float*)d_in[4];
    const float* w2 = (const float*)d_in[5];
    const float* b2 = (const float*)d_in[6];
    const float* w3 = (const float*)d_in[7];
    const float* b3 = (const float*)d_in[8];
    const float* w4 = (const float*)d_in[9];
    const float* b4 = (const float*)d_in[10];
    const float* wc = (const float*)d_in[11];
    const float* bc = (const float*)d_in[12];
    float* out = (float*)d_out;

    cudaFuncSetAttribute(lpg_fused_kernel,
                         cudaFuncAttributeMaxDynamicSharedMemorySize, SMEM_BYTES);

    lpg_fused_kernel<<<NCTA, NTHR, SMEM_BYTES>>>(x, w0, b0, w1, b1, w2, b2,
                                                 w3, b3, w4, b4, wc, bc, out);
}

// round 10
// speedup vs baseline: 2.1372x; 2.1372x over previous
#include <cuda_runtime.h>
#include <math.h>
#include <stdint.h>

#define NB    16
#define H8    44
#define W8    144
#define HWLO  (H8 * W8)        // 6336
#define NPIX  (NB * HWLO)      // 101376
#define HOUT  (H8 * 8)         // 352
#define WOUT  (W8 * 8)         // 1152
#define P     128              // pixels per tile
#define NTILES (NPIX / P)      // 792
#define NTHR  256
#define PI_F  3.1415926535f
#define MAX_DEPTH 81.0f

typedef unsigned long long u64;

#define XPITCH 136             // Xs row pitch (B-frag loads conflict-free)
#define WPITCH 132             // W0s row pitch (A-frag loads conflict-free)
#define APITCH 132             // a1s/a2s row pitch

// ---- smem layout (float offsets) ----
#define OFF_XS    0            // [128 ch][136] tf32 bits = 17408 f
#define OFF_A1S   0            // alias: a1 [64][132] = 8448 f
#define OFF_A2S   8448         // alias: a2 [32][132] = 4224 f -> 12672
#define OFF_PLN   12672        // alias: [4][128] = 512 f -> 13184 (< 17408)
#define OFF_W0S   17408        // [64][132] tf32 bits = 8448 f -> 25856
#define OFF_WT1   25856        // 2048 -> 27904
#define OFF_WT2   27904        // 512  -> 28416
#define OFF_WT3   28416        // 128  -> 28544
#define OFF_WT4   28544        // 32   -> 28576
#define OFF_WC    28576        // 16   -> 28592
#define OFF_B0    28592        // 64
#define OFF_B1    28656        // 32
#define OFF_B2    28688        // 16
#define OFF_B3    28704        // 8
#define OFF_B4    28712        // 4
#define OFF_BC    28716        // 4
#define SMEM_FLOATS 28720
#define SMEM_BYTES  (SMEM_FLOATS * 4)   // 114880 B -> 1 CTA/SM

// ---------------- helpers -------------------------------------------------------
__device__ __forceinline__ uint32_t tf32u(float v) {
    uint32_t r; asm("cvt.rna.tf32.f32 %0, %1;" : "=r"(r) : "f"(v)); return r;
}
__device__ __forceinline__ u64 pack2(float lo, float hi) {
    u64 r; asm("mov.b64 %0, {%1, %2};" : "=l"(r) : "f"(lo), "f"(hi)); return r;
}
__device__ __forceinline__ void unpack2(u64 v, float& lo, float& hi) {
    asm("mov.b64 {%0, %1}, %2;" : "=f"(lo), "=f"(hi) : "l"(v));
}
__device__ __forceinline__ u64 fma2(u64 a, u64 b, u64 c) {
    u64 d; asm("fma.rn.f32x2 %0, %1, %2, %3;" : "=l"(d) : "l"(a), "l"(b), "l"(c));
    return d;
}
__device__ __forceinline__ float eluf(float v) {
    return fmaxf(v, 0.0f) + (__expf(fminf(v, 0.0f)) - 1.0f);
}
__device__ __forceinline__ float sigmoidf_fast(float v) {
    return __fdividef(1.0f, 1.0f + __expf(-v));
}
// tf32 m16n8k8: D += A x B (A row-major 16x8, B col-major 8x8, fp32 acc)
__device__ __forceinline__ void mma8(float* d, uint32_t a0, uint32_t a1, uint32_t a2,
                                     uint32_t a3, uint32_t b0, uint32_t b1) {
    asm volatile(
        "mma.sync.aligned.m16n8k8.row.col.f32.tf32.tf32.f32 "
        "{%0,%1,%2,%3}, {%4,%5,%6,%7}, {%8,%9}, {%0,%1,%2,%3};"
        : "+f"(d[0]), "+f"(d[1]), "+f"(d[2]), "+f"(d[3])
        : "r"(a0), "r"(a1), "r"(a2), "r"(a3), "r"(b0), "r"(b1));
}

// ---------------------------------- kernel ------------------------------------
__global__ __launch_bounds__(NTHR, 1) void lpg_mma_kernel(
    const float* __restrict__ x,
    const float* __restrict__ w0, const float* __restrict__ b0,
    const float* __restrict__ w1, const float* __restrict__ b1,
    const float* __restrict__ w2, const float* __restrict__ b2,
    const float* __restrict__ w3, const float* __restrict__ b3,
    const float* __restrict__ w4, const float* __restrict__ b4,
    const float* __restrict__ wc, const float* __restrict__ bc,
    float* __restrict__ out)
{
    extern __shared__ float sm[];
    uint32_t* Xsu  = (uint32_t*)(sm + OFF_XS);    // [128][XPITCH] tf32 bits
    uint32_t* W0su = (uint32_t*)(sm + OFF_W0S);   // [64][WPITCH]  tf32 bits
    float* a1s = sm + OFF_A1S;
    float* a2s = sm + OFF_A2S;
    float* pln = sm + OFF_PLN;
    float* wT1 = sm + OFF_WT1;
    float* wT2 = sm + OFF_WT2;
    float* wT3 = sm + OFF_WT3;
    float* wT4 = sm + OFF_WT4;
    float* sWc = sm + OFF_WC;
    float* sB0 = sm + OFF_B0;
    float* sB1 = sm + OFF_B1;
    float* sB2 = sm + OFF_B2;
    float* sB3 = sm + OFF_B3;
    float* sB4 = sm + OFF_B4;
    float* sBc = sm + OFF_BC;

    const int t   = threadIdx.x;
    const int wid = t >> 5;
    const int lid = t & 31;
    const int p0  = blockIdx.x * P;

    // ---- stage X tile [128ch][128pix] (tf32, channel-major, coalesced) ----------
#pragma unroll
    for (int i = 0; i < 16; i++) {
        const int j  = t + i * 256;           // 0..4095
        const int c  = j >> 5;                // channel
        const int g  = j & 31;                // 4-pixel group
        const int p  = p0 + 4 * g;
        const int bb = p / HWLO;
        const int hw = p - bb * HWLO;
        const float4 v = __ldg((const float4*)(x + ((size_t)(bb * 128 + c)) * HWLO + hw));
        uint4 u; u.x = tf32u(v.x); u.y = tf32u(v.y); u.z = tf32u(v.z); u.w = tf32u(v.w);
        *(uint4*)(Xsu + c * XPITCH + 4 * g) = u;
    }
    // ---- stage W0 [64][128] (tf32) ------------------------------------------------
    for (int j = t; j < 64 * 128; j += NTHR) {
        const int o = j >> 7, c = j & 127;
        W0su[o * WPITCH + c] = tf32u(w0[j]);
    }
    // ---- stage small weights (transposed) + biases --------------------------------
    for (int j = t; j < 64 * 32; j += NTHR) { int o = j >> 6, c = j & 63; wT1[c * 32 + o] = w1[j]; }
    for (int j = t; j < 32 * 16; j += NTHR) { int o = j >> 5, c = j & 31; wT2[c * 16 + o] = w2[j]; }
    if (t < 128) { int o = t >> 4, c = t & 15; wT3[c * 8 + o] = w3[t]; }
    if (t < 32)  { int o = t >> 3, c = t & 7;  wT4[c * 4 + o] = w4[t]; }
    if (t < 12)  { int o = t >> 2, c = t & 3;  sWc[c * 3 + o] = wc[t]; }
    if (t < 64) sB0[t] = b0[t];
    if (t < 32) sB1[t] = b1[t];
    if (t < 16) sB2[t] = b2[t];
    if (t < 8)  sB3[t] = b3[t];
    if (t < 4)  sB4[t] = b4[t];
    if (t < 3)  sBc[t] = bc[t];
    __syncthreads();

    // ---- layer 1 via tf32 mma.sync: D[64][128] = W0 x X ---------------------------
    const int rb  = wid & 3;        // out row band (16 rows)
    const int chh = wid >> 2;       // pixel half (64 pix)
    const int g   = lid >> 2;       // groupID
    const int r   = lid & 3;        // threadID in group

    float d[8][4];
#pragma unroll
    for (int n = 0; n < 8; n++) { d[n][0] = d[n][1] = d[n][2] = d[n][3] = 0.0f; }

    const uint32_t* W0r0 = W0su + (rb * 16 + g) * WPITCH;
    const uint32_t* W0r1 = W0r0 + 8 * WPITCH;

#pragma unroll
    for (int k0 = 0; k0 < 128; k0 += 8) {
        const uint32_t a0 = W0r0[k0 + r];
        const uint32_t a1 = W0r1[k0 + r];
        const uint32_t a2 = W0r0[k0 + r + 4];
        const uint32_t a3 = W0r1[k0 + r + 4];
        const uint32_t* Bk0 = Xsu + (k0 + r) * XPITCH + chh * 64 + g;
        const uint32_t* Bk1 = Bk0 + 4 * XPITCH;
#pragma unroll
        for (int n = 0; n < 8; n++) {
            mma8(d[n], a0, a1, a2, a3, Bk0[n * 8], Bk1[n * 8]);
        }
    }
    __syncthreads();    // all Xs reads done before a1s (alias) writes

    // ---- bias + ELU + store a1 fragments ------------------------------------------
    {
        const int row0 = rb * 16 + g;
        const int row1 = row0 + 8;
        const float bz0 = sB0[row0];
        const float bz1 = sB0[row1];
#pragma unroll
        for (int n = 0; n < 8; n++) {
            const int px = chh * 64 + n * 8 + 2 * r;
            *(float2*)(a1s + row0 * APITCH + px) =
                make_float2(eluf(d[n][0] + bz0), eluf(d[n][1] + bz0));
            *(float2*)(a1s + row1 * APITCH + px) =
                make_float2(eluf(d[n][2] + bz1), eluf(d[n][3] + bz1));
        }
    }
    __syncthreads();

    // ---- layer 2 (fp32 packed): 64 -> 32, frag = 4 pix x 4 outs --------------------
    const int pg = t & 31;
    const int og = t >> 5;
    const int pl = 4 * pg;
    {
        const u64* b1p = (const u64*)sB1;
        const float* __restrict__ wrow = wT1 + og * 4;
        u64 a2[4][2];
#pragma unroll
        for (int j = 0; j < 2; j++) {
            const u64 bv = b1p[og * 2 + j];
            a2[0][j] = bv; a2[1][j] = bv; a2[2][j] = bv; a2[3][j] = bv;
        }
#pragma unroll 4
        for (int c = 0; c < 64; c++) {
            const float4 av = *(const float4*)(a1s + c * APITCH + pl);
            const ulonglong2 w = *(const ulonglong2*)(wrow + c * 32);
            const u64 x0 = pack2(av.x, av.x), x1 = pack2(av.y, av.y);
            const u64 x2 = pack2(av.z, av.z), x3 = pack2(av.w, av.w);
            a2[0][0] = fma2(w.x, x0, a2[0][0]); a2[0][1] = fma2(w.y, x0, a2[0][1]);
            a2[1][0] = fma2(w.x, x1, a2[1][0]); a2[1][1] = fma2(w.y, x1, a2[1][1]);
            a2[2][0] = fma2(w.x, x2, a2[2][0]); a2[2][1] = fma2(w.y, x2, a2[2][1]);
            a2[3][0] = fma2(w.x, x3, a2[3][0]); a2[3][1] = fma2(w.y, x3, a2[3][1]);
        }
#pragma unroll
        for (int j = 0; j < 2; j++) {
            float l0, h0, l1, h1, l2, h2, l3, h3;
            unpack2(a2[0][j], l0, h0); unpack2(a2[1][j], l1, h1);
            unpack2(a2[2][j], l2, h2); unpack2(a2[3][j], l3, h3);
            const int o0 = og * 4 + 2 * j;
            *(float4*)(a2s + o0 * APITCH + pl)       = make_float4(eluf(l0), eluf(l1), eluf(l2), eluf(l3));
            *(float4*)(a2s + (o0 + 1) * APITCH + pl) = make_float4(eluf(h0), eluf(h1), eluf(h2), eluf(h3));
        }
    }
    __syncthreads();

    // ---- tail: 1 thread per pixel -> plane params ----------------------------------
    if (t < P) {
        float a3[16];
        {
            const u64* b2p = (const u64*)sB2;
            u64 acc3[8];
#pragma unroll
            for (int j = 0; j < 8; j++) acc3[j] = b2p[j];
#pragma unroll 4
            for (int c = 0; c < 32; c++) {
                const float v = a2s[c * APITCH + t];
                const u64 xx = pack2(v, v);
                const ulonglong2 wa = *(const ulonglong2*)(wT2 + c * 16);
                const ulonglong2 wb = *(const ulonglong2*)(wT2 + c * 16 + 4);
                const ulonglong2 wc2 = *(const ulonglong2*)(wT2 + c * 16 + 8);
                const ulonglong2 wd = *(const ulonglong2*)(wT2 + c * 16 + 12);
                acc3[0] = fma2(wa.x, xx, acc3[0]);  acc3[1] = fma2(wa.y, xx, acc3[1]);
                acc3[2] = fma2(wb.x, xx, acc3[2]);  acc3[3] = fma2(wb.y, xx, acc3[3]);
                acc3[4] = fma2(wc2.x, xx, acc3[4]); acc3[5] = fma2(wc2.y, xx, acc3[5]);
                acc3[6] = fma2(wd.x, xx, acc3[6]);  acc3[7] = fma2(wd.y, xx, acc3[7]);
            }
#pragma unroll
            for (int j = 0; j < 8; j++) {
                float lo, hi; unpack2(acc3[j], lo, hi);
                a3[2 * j] = eluf(lo); a3[2 * j + 1] = eluf(hi);
            }
        }
        float a4[8];
        {
            const u64* b3p = (const u64*)sB3;
            u64 acc4[4];
#pragma unroll
            for (int j = 0; j < 4; j++) acc4[j] = b3p[j];
#pragma unroll
            for (int c = 0; c < 16; c++) {
                const u64 xx = pack2(a3[c], a3[c]);
                const ulonglong2 wa = *(const ulonglong2*)(wT3 + c * 8);
                const ulonglong2 wb = *(const ulonglong2*)(wT3 + c * 8 + 4);
                acc4[0] = fma2(wa.x, xx, acc4[0]); acc4[1] = fma2(wa.y, xx, acc4[1]);
                acc4[2] = fma2(wb.x, xx, acc4[2]); acc4[3] = fma2(wb.y, xx, acc4[3]);
            }
#pragma unroll
            for (int j = 0; j < 4; j++) {
                float lo, hi; unpack2(acc4[j], lo, hi);
                a4[2 * j] = eluf(lo); a4[2 * j + 1] = eluf(hi);
            }
        }
        float a5[4];
        {
            const u64* b4p = (const u64*)sB4;
            u64 acc5[2];
            acc5[0] = b4p[0]; acc5[1] = b4p[1];
#pragma unroll
            for (int c = 0; c < 8; c++) {
                const u64 xx = pack2(a4[c], a4[c]);
                const ulonglong2 w = *(const ulonglong2*)(wT4 + c * 4);
                acc5[0] = fma2(w.x, xx, acc5[0]); acc5[1] = fma2(w.y, xx, acc5[1]);
            }
            unpack2(acc5[0], a5[0], a5[1]); unpack2(acc5[1], a5[2], a5[3]);
        }
        float y[3];
#pragma unroll
        for (int o = 0; o < 3; o++) {
            float s = sBc[o];
#pragma unroll
            for (int c = 0; c < 4; c++) s += sWc[c * 3 + o] * a5[c];
            y[o] = s;
        }
        const float theta = sigmoidf_fast(y[0]) * (PI_F / 6.0f);
        const float phi   = sigmoidf_fast(y[1]) * (PI_F * 2.0f);
        const float dist  = sigmoidf_fast(y[2]) * MAX_DEPTH;
        const float st = __sinf(theta), ct = __cosf(theta);
        const float sp = __sinf(phi),   cp = __cosf(phi);
        float nx = st * cp, ny = st * sp, nz = ct;
        const float inv = rsqrtf(nx * nx + ny * ny + nz * nz);
        pln[0 * 128 + t] = nx * inv;
        pln[1 * 128 + t] = ny * inv;
        pln[2 * 128 + t] = nz * inv;
        pln[3 * 128 + t] = dist;
    }
    __syncthreads();

    // ---- epilogue: 2 threads per pixel, 4 rows each ---------------------------------
    {
        const int px   = t >> 1;
        const int half = t & 1;
        const float nx   = pln[0 * 128 + px];
        const float ny   = pln[1 * 128 + px];
        const float nz   = pln[2 * 128 + px];
        const float dist = pln[3 * 128 + px];

        const int p  = p0 + px;
        const int bb = p / HWLO;
        const int hw = p - bb * HWLO;
        const int h  = hw / W8;
        const int w  = hw - h * W8;
        float* __restrict__ op = out + ((size_t)bb * HOUT + (size_t)h * 8) * WOUT + (size_t)w * 8;

#pragma unroll
        for (int rr = 0; rr < 4; rr++) {
            const int i = half * 4 + rr;
            const float vterm = ny * ((float)i - 3.5f) * 0.125f + nz;
            float row[8];
#pragma unroll
            for (int j = 0; j < 8; j++) {
                const float u = ((float)j - 3.5f) * 0.125f;
                row[j] = __fdividef(dist, nx * u + vterm);
            }
            float4* o4 = (float4*)(op + (size_t)i * WOUT);
            o4[0] = make_float4(row[0], row[1], row[2], row[3]);
            o4[1] = make_float4(row[4], row[5], row[6], row[7]);
        }
    }
}

extern "C" void kernel_launch(void* const* d_in, const int* in_sizes, int n_in,
                              void* d_out, int out_size) {
    const float* x  = (const float*)d_in[0];
    const float* w0 = (const float*)d_in[1];
    const float* b0 = (const float*)d_in[2];
    const float* w1 = (const float*)d_in[3];
    const float* b1 = (const float*)d_in[4];
    const float* w2 = (const float*)d_in[5];
    const float* b2 = (const float*)d_in[6];
    const float* w3 = (const float*)d_in[7];
    const float* b3 = (const float*)d_in[8];
    const float* w4 = (const float*)d_in[9];
    const float* b4 = (const float*)d_in[10];
    const float* wc = (const float*)d_in[11];
    const float* bc = (const float*)d_in[12];
    float* out = (float*)d_out;

    cudaFuncSetAttribute(lpg_mma_kernel,
                         cudaFuncAttributeMaxDynamicSharedMemorySize, SMEM_BYTES);

    lpg_mma_kernel<<<NTILES, NTHR, SMEM_BYTES>>>(x, w0, b0, w1, b1, w2, b2,
                                                 w3, b3, w4, b4, wc, bc, out);
}

// round 11
// speedup vs baseline: 2.5968x; 1.2151x over previous
#include <cuda_runtime.h>
#include <math.h>
#include <stdint.h>

#define NB    16
#define H8    44
#define W8    144
#define HWLO  (H8 * W8)        // 6336
#define NPIX  (NB * HWLO)      // 101376
#define HOUT  (H8 * 8)         // 352
#define WOUT  (W8 * 8)         // 1152
#define P     128              // pixels per tile
#define NTILES (NPIX / P)      // 792
#define NTHR  256
#define PI_F  3.1415926535f
#define MAX_DEPTH 81.0f

typedef unsigned long long u64;

#define XPITCH 136             // Xs / a1su / a2su pitch (B-frag conflict-free)
#define WPITCH 132             // W0s pitch
#define W1P    68              // W1s pitch
#define W2P    36              // W2s pitch
#define A3P    132             // a3s pitch

// ---- smem layout (float offsets) ----
#define OFF_XS    0            // [128][136] = 17408 f
#define OFF_A1SU  0            // alias: a1 tf32 [64][136] = 8704
#define OFF_A2SU  8704         // alias: a2 tf32 [32][136] = 4352 -> 13056
#define OFF_A3S   13056        // alias: a3 f32 [16][132]  = 2112 -> 15168
#define OFF_PLN   15168        // alias: [4][128] = 512 -> 15680 (< 17408)
#define OFF_W0S   17408        // [64][132] tf32 = 8448 -> 25856
#define OFF_W1S   25856        // [32][68]  tf32 = 2176 -> 28032
#define OFF_W2S   28032        // [16][36]  tf32 = 576  -> 28608
#define OFF_WT3   28608        // [16][8] = 128 -> 28736
#define OFF_WT4   28736        // [8][4]  = 32  -> 28768
#define OFF_WC    28768        // 16 -> 28784
#define OFF_B0    28784        // 64
#define OFF_B1    28848        // 32
#define OFF_B2    28880        // 16
#define OFF_B3    28896        // 8
#define OFF_B4    28904        // 4
#define OFF_BC    28908        // 4
#define SMEM_FLOATS 28912
#define SMEM_BYTES  (SMEM_FLOATS * 4)   // 115648 B -> 1 CTA/SM

// ---------------- helpers -------------------------------------------------------
__device__ __forceinline__ uint32_t tf32u(float v) {
    uint32_t r; asm("cvt.rna.tf32.f32 %0, %1;" : "=r"(r) : "f"(v)); return r;
}
__device__ __forceinline__ u64 pack2(float lo, float hi) {
    u64 r; asm("mov.b64 %0, {%1, %2};" : "=l"(r) : "f"(lo), "f"(hi)); return r;
}
__device__ __forceinline__ void unpack2(u64 v, float& lo, float& hi) {
    asm("mov.b64 {%0, %1}, %2;" : "=f"(lo), "=f"(hi) : "l"(v));
}
__device__ __forceinline__ u64 fma2(u64 a, u64 b, u64 c) {
    u64 d; asm("fma.rn.f32x2 %0, %1, %2, %3;" : "=l"(d) : "l"(a), "l"(b), "l"(c));
    return d;
}
__device__ __forceinline__ float eluf(float v) {
    return fmaxf(v, 0.0f) + (__expf(fminf(v, 0.0f)) - 1.0f);
}
__device__ __forceinline__ float sigmoidf_fast(float v) {
    return __fdividef(1.0f, 1.0f + __expf(-v));
}
// tf32 m16n8k8: D += A x B (A row-major 16x8, B col-major 8x8, fp32 acc)
__device__ __forceinline__ void mma8(float* d, uint32_t a0, uint32_t a1, uint32_t a2,
                                     uint32_t a3, uint32_t b0, uint32_t b1) {
    asm volatile(
        "mma.sync.aligned.m16n8k8.row.col.f32.tf32.tf32.f32 "
        "{%0,%1,%2,%3}, {%4,%5,%6,%7}, {%8,%9}, {%0,%1,%2,%3};"
        : "+f"(d[0]), "+f"(d[1]), "+f"(d[2]), "+f"(d[3])
        : "r"(a0), "r"(a1), "r"(a2), "r"(a3), "r"(b0), "r"(b1));
}

// ---------------------------------- kernel ------------------------------------
__global__ __launch_bounds__(NTHR, 1) void lpg_mma_kernel(
    const float* __restrict__ x,
    const float* __restrict__ w0, const float* __restrict__ b0,
    const float* __restrict__ w1, const float* __restrict__ b1,
    const float* __restrict__ w2, const float* __restrict__ b2,
    const float* __restrict__ w3, const float* __restrict__ b3,
    const float* __restrict__ w4, const float* __restrict__ b4,
    const float* __restrict__ wc, const float* __restrict__ bc,
    float* __restrict__ out)
{
    extern __shared__ float sm[];
    uint32_t* Xsu  = (uint32_t*)(sm + OFF_XS);
    uint32_t* a1su = (uint32_t*)(sm + OFF_A1SU);
    uint32_t* a2su = (uint32_t*)(sm + OFF_A2SU);
    float*    a3s  = sm + OFF_A3S;
    float*    pln  = sm + OFF_PLN;
    uint32_t* W0su = (uint32_t*)(sm + OFF_W0S);
    uint32_t* W1su = (uint32_t*)(sm + OFF_W1S);
    uint32_t* W2su = (uint32_t*)(sm + OFF_W2S);
    float* wT3 = sm + OFF_WT3;
    float* wT4 = sm + OFF_WT4;
    float* sWc = sm + OFF_WC;
    float* sB0 = sm + OFF_B0;
    float* sB1 = sm + OFF_B1;
    float* sB2 = sm + OFF_B2;
    float* sB3 = sm + OFF_B3;
    float* sB4 = sm + OFF_B4;
    float* sBc = sm + OFF_BC;

    const int t   = threadIdx.x;
    const int wid = t >> 5;
    const int lid = t & 31;
    const int p0  = blockIdx.x * P;
    const int g   = lid >> 2;      // MMA groupID
    const int r   = lid & 3;       // MMA threadID-in-group

    // ---- stage X tile [128ch][128pix] tf32 (hoisted pixel indexing) -------------
    {
        const int gg = t & 31;               // 4-pixel group (invariant over i)
        const int c0 = t >> 5;               // channel base
        const int p  = p0 + 4 * gg;
        const int bb = p / HWLO;
        const int hw = p - bb * HWLO;
        const float* __restrict__ xbase = x + ((size_t)bb * 128) * HWLO + hw;
#pragma unroll
        for (int i = 0; i < 16; i++) {
            const int c = c0 + i * 8;
            const float4 v = __ldg((const float4*)(xbase + (size_t)c * HWLO));
            uint4 u; u.x = tf32u(v.x); u.y = tf32u(v.y); u.z = tf32u(v.z); u.w = tf32u(v.w);
            *(uint4*)(Xsu + c * XPITCH + 4 * gg) = u;
        }
    }
    // ---- stage weights (tf32 for MMA layers, transposed fp32 for tail) -----------
    for (int j = t; j < 64 * 128; j += NTHR) { int o = j >> 7, c = j & 127; W0su[o * WPITCH + c] = tf32u(w0[j]); }
    for (int j = t; j < 32 * 64;  j += NTHR) { int o = j >> 6, c = j & 63;  W1su[o * W1P + c]    = tf32u(w1[j]); }
    for (int j = t; j < 16 * 32;  j += NTHR) { int o = j >> 5, c = j & 31;  W2su[o * W2P + c]    = tf32u(w2[j]); }
    if (t < 128) { int o = t >> 4, c = t & 15; wT3[c * 8 + o] = w3[t]; }
    if (t < 32)  { int o = t >> 3, c = t & 7;  wT4[c * 4 + o] = w4[t]; }
    if (t < 12)  { int o = t >> 2, c = t & 3;  sWc[c * 3 + o] = wc[t]; }
    if (t < 64) sB0[t] = b0[t];
    if (t < 32) sB1[t] = b1[t];
    if (t < 16) sB2[t] = b2[t];
    if (t < 8)  sB3[t] = b3[t];
    if (t < 4)  sB4[t] = b4[t];
    if (t < 3)  sBc[t] = bc[t];
    __syncthreads();

    // ============ layer 1 MMA: D[64][128] = W0 x X ================================
    {
        const int rb  = wid & 3;       // row band (16 outs)
        const int chh = wid >> 2;      // pixel half
        float d[8][4];
#pragma unroll
        for (int n = 0; n < 8; n++) { d[n][0] = d[n][1] = d[n][2] = d[n][3] = 0.0f; }
        const uint32_t* W0r0 = W0su + (rb * 16 + g) * WPITCH;
        const uint32_t* W0r1 = W0r0 + 8 * WPITCH;
#pragma unroll
        for (int k0 = 0; k0 < 128; k0 += 8) {
            const uint32_t a0 = W0r0[k0 + r];
            const uint32_t a1 = W0r1[k0 + r];
            const uint32_t a2 = W0r0[k0 + r + 4];
            const uint32_t a3 = W0r1[k0 + r + 4];
            const uint32_t* Bk0 = Xsu + (k0 + r) * XPITCH + chh * 64 + g;
            const uint32_t* Bk1 = Bk0 + 4 * XPITCH;
#pragma unroll
            for (int n = 0; n < 8; n++) mma8(d[n], a0, a1, a2, a3, Bk0[n * 8], Bk1[n * 8]);
        }
        __syncthreads();               // Xs dead -> a1su (alias) writable

        const int row0 = rb * 16 + g;
        const int row1 = row0 + 8;
        const float bz0 = sB0[row0];
        const float bz1 = sB0[row1];
#pragma unroll
        for (int n = 0; n < 8; n++) {
            const int px = chh * 64 + n * 8 + 2 * r;
            uint2 u0, u1;
            u0.x = tf32u(eluf(d[n][0] + bz0)); u0.y = tf32u(eluf(d[n][1] + bz0));
            u1.x = tf32u(eluf(d[n][2] + bz1)); u1.y = tf32u(eluf(d[n][3] + bz1));
            *(uint2*)(a1su + row0 * XPITCH + px) = u0;
            *(uint2*)(a1su + row1 * XPITCH + px) = u1;
        }
    }
    __syncthreads();

    // ============ layer 2 MMA: D[32][128] = W1 x a1 ===============================
    {
        const int rb  = wid & 1;       // row band (16 of 32 outs)
        const int wq  = wid >> 1;      // pixel quarter (32 pix)
        float d[4][4];
#pragma unroll
        for (int n = 0; n < 4; n++) { d[n][0] = d[n][1] = d[n][2] = d[n][3] = 0.0f; }
        const uint32_t* W1r0 = W1su + (rb * 16 + g) * W1P;
        const uint32_t* W1r1 = W1r0 + 8 * W1P;
#pragma unroll
        for (int k0 = 0; k0 < 64; k0 += 8) {
            const uint32_t a0 = W1r0[k0 + r];
            const uint32_t a1 = W1r1[k0 + r];
            const uint32_t a2 = W1r0[k0 + r + 4];
            const uint32_t a3 = W1r1[k0 + r + 4];
            const uint32_t* Bk0 = a1su + (k0 + r) * XPITCH + wq * 32 + g;
            const uint32_t* Bk1 = Bk0 + 4 * XPITCH;
#pragma unroll
            for (int n = 0; n < 4; n++) mma8(d[n], a0, a1, a2, a3, Bk0[n * 8], Bk1[n * 8]);
        }
        // a2su disjoint from a1su -> no barrier needed before scatter
        const int row0 = rb * 16 + g;
        const int row1 = row0 + 8;
        const float bz0 = sB1[row0];
        const float bz1 = sB1[row1];
#pragma unroll
        for (int n = 0; n < 4; n++) {
            const int px = wq * 32 + n * 8 + 2 * r;
            uint2 u0, u1;
            u0.x = tf32u(eluf(d[n][0] + bz0)); u0.y = tf32u(eluf(d[n][1] + bz0));
            u1.x = tf32u(eluf(d[n][2] + bz1)); u1.y = tf32u(eluf(d[n][3] + bz1));
            *(uint2*)(a2su + row0 * XPITCH + px) = u0;
            *(uint2*)(a2su + row1 * XPITCH + px) = u1;
        }
    }
    __syncthreads();

    // ============ layer 3 MMA: D[16][128] = W2 x a2 ===============================
    {
        float d[2][4];
#pragma unroll
        for (int n = 0; n < 2; n++) { d[n][0] = d[n][1] = d[n][2] = d[n][3] = 0.0f; }
        const uint32_t* W2r0 = W2su + g * W2P;
        const uint32_t* W2r1 = W2r0 + 8 * W2P;
#pragma unroll
        for (int k0 = 0; k0 < 32; k0 += 8) {
            const uint32_t a0 = W2r0[k0 + r];
            const uint32_t a1 = W2r1[k0 + r];
            const uint32_t a2 = W2r0[k0 + r + 4];
            const uint32_t a3 = W2r1[k0 + r + 4];
            const uint32_t* Bk0 = a2su + (k0 + r) * XPITCH + wid * 16 + g;
            const uint32_t* Bk1 = Bk0 + 4 * XPITCH;
#pragma unroll
            for (int n = 0; n < 2; n++) mma8(d[n], a0, a1, a2, a3, Bk0[n * 8], Bk1[n * 8]);
        }
        const float bz0 = sB2[g];
        const float bz1 = sB2[g + 8];
#pragma unroll
        for (int n = 0; n < 2; n++) {
            const int px = wid * 16 + n * 8 + 2 * r;
            *(float2*)(a3s + g * A3P + px) =
                make_float2(eluf(d[n][0] + bz0), eluf(d[n][1] + bz0));
            *(float2*)(a3s + (g + 8) * A3P + px) =
                make_float2(eluf(d[n][2] + bz1), eluf(d[n][3] + bz1));
        }
    }
    __syncthreads();

    // ---- tail: layers 4-6 per pixel (t < 128) -> plane params --------------------
    if (t < P) {
        float a3[16];
#pragma unroll
        for (int c = 0; c < 16; c++) a3[c] = a3s[c * A3P + t];

        float a4[8];
        {
            const u64* b3p = (const u64*)sB3;
            u64 acc4[4];
#pragma unroll
            for (int j = 0; j < 4; j++) acc4[j] = b3p[j];
#pragma unroll
            for (int c = 0; c < 16; c++) {
                const u64 xx = pack2(a3[c], a3[c]);
                const ulonglong2 wa = *(const ulonglong2*)(wT3 + c * 8);
                const ulonglong2 wb = *(const ulonglong2*)(wT3 + c * 8 + 4);
                acc4[0] = fma2(wa.x, xx, acc4[0]); acc4[1] = fma2(wa.y, xx, acc4[1]);
                acc4[2] = fma2(wb.x, xx, acc4[2]); acc4[3] = fma2(wb.y, xx, acc4[3]);
            }
#pragma unroll
            for (int j = 0; j < 4; j++) {
                float lo, hi; unpack2(acc4[j], lo, hi);
                a4[2 * j] = eluf(lo); a4[2 * j + 1] = eluf(hi);
            }
        }
        float a5[4];
        {
            const u64* b4p = (const u64*)sB4;
            u64 acc5[2];
            acc5[0] = b4p[0]; acc5[1] = b4p[1];
#pragma unroll
            for (int c = 0; c < 8; c++) {
                const u64 xx = pack2(a4[c], a4[c]);
                const ulonglong2 w = *(const ulonglong2*)(wT4 + c * 4);
                acc5[0] = fma2(w.x, xx, acc5[0]); acc5[1] = fma2(w.y, xx, acc5[1]);
            }
            unpack2(acc5[0], a5[0], a5[1]); unpack2(acc5[1], a5[2], a5[3]);
        }
        float y[3];
#pragma unroll
        for (int o = 0; o < 3; o++) {
            float s = sBc[o];
#pragma unroll
            for (int c = 0; c < 4; c++) s += sWc[c * 3 + o] * a5[c];
            y[o] = s;
        }
        const float theta = sigmoidf_fast(y[0]) * (PI_F / 6.0f);
        const float phi   = sigmoidf_fast(y[1]) * (PI_F * 2.0f);
        const float dist  = sigmoidf_fast(y[2]) * MAX_DEPTH;
        const float st = __sinf(theta), ct = __cosf(theta);
        const float sp = __sinf(phi),   cp = __cosf(phi);
        float nx = st * cp, ny = st * sp, nz = ct;
        const float inv = rsqrtf(nx * nx + ny * ny + nz * nz);
        pln[0 * 128 + t] = nx * inv;
        pln[1 * 128 + t] = ny * inv;
        pln[2 * 128 + t] = nz * inv;
        pln[3 * 128 + t] = dist;
    }
    __syncthreads();

    // ---- epilogue: 2 threads per pixel, 4 rows each -------------------------------
    {
        const int px   = t >> 1;
        const int half = t & 1;
        const float nx   = pln[0 * 128 + px];
        const float ny   = pln[1 * 128 + px];
        const float nz   = pln[2 * 128 + px];
        const float dist = pln[3 * 128 + px];

        const int p  = p0 + px;
        const int bb = p / HWLO;
        const int hw = p - bb * HWLO;
        const int h  = hw / W8;
        const int w  = hw - h * W8;
        float* __restrict__ op = out + ((size_t)bb * HOUT + (size_t)h * 8) * WOUT + (size_t)w * 8;

#pragma unroll
        for (int rr = 0; rr < 4; rr++) {
            const int i = half * 4 + rr;
            const float vterm = ny * ((float)i - 3.5f) * 0.125f + nz;
            float row[8];
#pragma unroll
            for (int j = 0; j < 8; j++) {
                const float u = ((float)j - 3.5f) * 0.125f;
                row[j] = __fdividef(dist, nx * u + vterm);
            }
            float4* o4 = (float4*)(op + (size_t)i * WOUT);
            o4[0] = make_float4(row[0], row[1], row[2], row[3]);
            o4[1] = make_float4(row[4], row[5], row[6], row[7]);
        }
    }
}

extern "C" void kernel_launch(void* const* d_in, const int* in_sizes, int n_in,
                              void* d_out, int out_size) {
    const float* x  = (const float*)d_in[0];
    const float* w0 = (const float*)d_in[1];
    const float* b0 = (const float*)d_in[2];
    const float* w1 = (const float*)d_in[3];
    const float* b1 = (const float*)d_in[4];
    const float* w2 = (const float*)d_in[5];
    const float* b2 = (const float*)d_in[6];
    const float* w3 = (const float*)d_in[7];
    const float* b3 = (const float*)d_in[8];
    const float* w4 = (const float*)d_in[9];
    const float* b4 = (const float*)d_in[10];
    const float* wc = (const float*)d_in[11];
    const float* bc = (const float*)d_in[12];
    float* out = (float*)d_out;

    cudaFuncSetAttribute(lpg_mma_kernel,
                         cudaFuncAttributeMaxDynamicSharedMemorySize, SMEM_BYTES);

    lpg_mma_kernel<<<NTILES, NTHR, SMEM_BYTES>>>(x, w0, b0, w1, b1, w2, b2,
                                                 w3, b3, w4, b4, wc, bc, out);
}

// round 12
// speedup vs baseline: 3.3082x; 1.2740x over previous
#include <cuda_runtime.h>
#include <math.h>
#include <stdint.h>

#define NB    16
#define H8    44
#define W8    144
#define HWLO  (H8 * W8)        // 6336
#define NPIX  (NB * HWLO)      // 101376
#define HOUT  (H8 * 8)         // 352
#define WOUT  (W8 * 8)         // 1152
#define P     128              // pixels per tile
#define NTILES (NPIX / P)      // 792
#define NTHR  256
#define PI_F  3.1415926535f
#define MAX_DEPTH 81.0f

typedef unsigned long long u64;

#define XPITCH 136             // Xs / a1s / a2s pitch (B-frag loads conflict-free)
#define WPITCH 132             // W0s pitch (A-frag loads conflict-free)
#define W1P    68              // W1s pitch
#define A3P    132             // a3s pitch

// ---- smem layout (float offsets) ----
#define OFF_XS    0            // [128][136] = 17408 f
#define OFF_A1S   0            // alias: a1 f32 [64][136] = 8704
#define OFF_A2S   8704         // alias: a2 f32 [32][136] = 4352 -> 13056
#define OFF_A3S   13056        // alias: a3 f32 [16][132] = 2112 -> 15168
#define OFF_PLN   15168        // alias: [4][128] = 512 -> 15680 (< 17408)
#define OFF_W0S   17408        // [64][132] raw f32 = 8448 -> 25856
#define OFF_W1S   25856        // [32][68]  raw f32 = 2176 -> 28032
#define OFF_WT3   28032        // [16][8] = 128 -> 28160
#define OFF_WT4   28160        // [8][4]  = 32  -> 28192
#define OFF_WC    28192        // 16 -> 28208
#define OFF_B0    28208        // 64
#define OFF_B1    28272        // 32
#define OFF_B2    28304        // 16
#define OFF_B3    28320        // 8
#define OFF_B4    28328        // 4
#define OFF_BC    28332        // 4
#define SMEM_FLOATS 28336
#define SMEM_BYTES  (SMEM_FLOATS * 4)   // 113344 B -> 2 CTAs/SM

// ---------------- helpers -------------------------------------------------------
__device__ __forceinline__ uint32_t smem_u32(const void* p) {
    uint32_t a;
    asm("{ .reg .u64 t; cvta.to.shared.u64 t, %1; cvt.u32.u64 %0, t; }" : "=r"(a) : "l"(p));
    return a;
}
__device__ __forceinline__ void cp_async16(uint32_t dst, const void* src) {
    asm volatile("cp.async.cg.shared.global [%0], [%1], 16;" :: "r"(dst), "l"(src));
}
#define CP_COMMIT() asm volatile("cp.async.commit_group;" ::: "memory")
#define CP_WAIT(N)  asm volatile("cp.async.wait_group %0;" :: "n"(N) : "memory")

__device__ __forceinline__ u64 pack2(float lo, float hi) {
    u64 r; asm("mov.b64 %0, {%1, %2};" : "=l"(r) : "f"(lo), "f"(hi)); return r;
}
__device__ __forceinline__ void unpack2(u64 v, float& lo, float& hi) {
    asm("mov.b64 {%0, %1}, %2;" : "=f"(lo), "=f"(hi) : "l"(v));
}
__device__ __forceinline__ u64 fma2(u64 a, u64 b, u64 c) {
    u64 d; asm("fma.rn.f32x2 %0, %1, %2, %3;" : "=l"(d) : "l"(a), "l"(b), "l"(c));
    return d;
}
__device__ __forceinline__ float eluf(float v) {
    return fmaxf(v, 0.0f) + (__expf(fminf(v, 0.0f)) - 1.0f);
}
__device__ __forceinline__ float sigmoidf_fast(float v) {
    return __fdividef(1.0f, 1.0f + __expf(-v));
}
// tf32 m16n8k8 (raw f32 bits as operands -> HW truncates to tf32)
__device__ __forceinline__ void mma8(float* d, uint32_t a0, uint32_t a1, uint32_t a2,
                                     uint32_t a3, uint32_t b0, uint32_t b1) {
    asm volatile(
        "mma.sync.aligned.m16n8k8.row.col.f32.tf32.tf32.f32 "
        "{%0,%1,%2,%3}, {%4,%5,%6,%7}, {%8,%9}, {%0,%1,%2,%3};"
        : "+f"(d[0]), "+f"(d[1]), "+f"(d[2]), "+f"(d[3])
        : "r"(a0), "r"(a1), "r"(a2), "r"(a3), "r"(b0), "r"(b1));
}

// ---------------------------------- kernel ------------------------------------
__global__ __launch_bounds__(NTHR, 2) void lpg_mma_kernel(
    const float* __restrict__ x,
    const float* __restrict__ w0, const float* __restrict__ b0,
    const float* __restrict__ w1, const float* __restrict__ b1,
    const float* __restrict__ w2, const float* __restrict__ b2,
    const float* __restrict__ w3, const float* __restrict__ b3,
    const float* __restrict__ w4, const float* __restrict__ b4,
    const float* __restrict__ wc, const float* __restrict__ bc,
    float* __restrict__ out)
{
    extern __shared__ float sm[];
    float*    a1s = sm + OFF_A1S;
    float*    a2s = sm + OFF_A2S;
    float*    a3s = sm + OFF_A3S;
    float*    pln = sm + OFF_PLN;
    float* wT3 = sm + OFF_WT3;
    float* wT4 = sm + OFF_WT4;
    float* sWc = sm + OFF_WC;
    float* sB0 = sm + OFF_B0;
    float* sB1 = sm + OFF_B1;
    float* sB2 = sm + OFF_B2;
    float* sB3 = sm + OFF_B3;
    float* sB4 = sm + OFF_B4;
    float* sBc = sm + OFF_BC;
    const uint32_t* Xsu  = (const uint32_t*)(sm + OFF_XS);
    const uint32_t* W0su = (const uint32_t*)(sm + OFF_W0S);
    const uint32_t* W1su = (const uint32_t*)(sm + OFF_W1S);

    const int t   = threadIdx.x;
    const int wid = t >> 5;
    const int lid = t & 31;
    const int p0  = blockIdx.x * P;
    const int g   = lid >> 2;      // MMA groupID
    const int r   = lid & 3;       // MMA threadID-in-group

    const uint32_t sbase = smem_u32(sm);

    // ---- staging via cp.async ----------------------------------------------------
    const int gg = t & 31;                    // 4-pixel group (X staging)
    const int c0 = t >> 5;
    {
        const int p  = p0 + 4 * gg;
        const int bb = p / HWLO;
        const int hw = p - bb * HWLO;
        const float* __restrict__ xbase = x + ((size_t)bb * 128) * HWLO + hw;
        // group 0: X channels 0..63
#pragma unroll
        for (int i = 0; i < 8; i++) {
            const int c = c0 + i * 8;
            cp_async16(sbase + (uint32_t)((OFF_XS + c * XPITCH + 4 * gg) * 4),
                       xbase + (size_t)c * HWLO);
        }
        CP_COMMIT();
        // group 1: X channels 64..127 + W0 + W1
#pragma unroll
        for (int i = 8; i < 16; i++) {
            const int c = c0 + i * 8;
            cp_async16(sbase + (uint32_t)((OFF_XS + c * XPITCH + 4 * gg) * 4),
                       xbase + (size_t)c * HWLO);
        }
    }
#pragma unroll
    for (int i = 0; i < 8; i++) {             // W0 [64][128] -> [64][132]
        const int j = t + i * 256;            // 0..2047 float4
        const int o = j >> 5, cq = j & 31;
        cp_async16(sbase + (uint32_t)((OFF_W0S + o * WPITCH + cq * 4) * 4),
                   w0 + o * 128 + cq * 4);
    }
#pragma unroll
    for (int i = 0; i < 2; i++) {             // W1 [32][64] -> [32][68]
        const int j = t + i * 256;            // 0..511 float4
        const int o = j >> 4, cq = j & 15;
        cp_async16(sbase + (uint32_t)((OFF_W1S + o * W1P + cq * 4) * 4),
                   w1 + o * 64 + cq * 4);
    }
    CP_COMMIT();

    // small manual staging (overlaps with cp.async in flight)
    if (t < 128) { int o = t >> 4, c = t & 15; wT3[c * 8 + o] = w3[t]; }
    if (t < 32)  { int o = t >> 3, c = t & 7;  wT4[c * 4 + o] = w4[t]; }
    if (t < 12)  { int o = t >> 2, c = t & 3;  sWc[c * 3 + o] = wc[t]; }
    if (t < 64) sB0[t] = b0[t];
    if (t < 32) sB1[t] = b1[t];
    if (t < 16) sB2[t] = b2[t];
    if (t < 8)  sB3[t] = b3[t];
    if (t < 4)  sB4[t] = b4[t];
    if (t < 3)  sBc[t] = bc[t];

    // preload layer-3 A fragments from global (w2 [16][32], L1/L2-hot)
    uint32_t a3f[16];
#pragma unroll
    for (int k0 = 0; k0 < 32; k0 += 8) {
        a3f[(k0 >> 3) * 4 + 0] = __float_as_uint(__ldg(w2 + g * 32 + k0 + r));
        a3f[(k0 >> 3) * 4 + 1] = __float_as_uint(__ldg(w2 + (g + 8) * 32 + k0 + r));
        a3f[(k0 >> 3) * 4 + 2] = __float_as_uint(__ldg(w2 + g * 32 + k0 + r + 4));
        a3f[(k0 >> 3) * 4 + 3] = __float_as_uint(__ldg(w2 + (g + 8) * 32 + k0 + r + 4));
    }

    CP_WAIT(1);                 // group 0 (X low half) landed
    __syncthreads();

    // ============ layer 1 MMA: D[64][128] = W0 x X (2 m-tiles x 4 n-tiles) ========
    const int mg = wid & 1;        // m-half: rows mg*32 .. mg*32+31
    const int nq = wid >> 1;       // pixel quarter (32 px)
    float d0[4][4], d1[4][4];
#pragma unroll
    for (int n = 0; n < 4; n++) {
        d0[n][0] = d0[n][1] = d0[n][2] = d0[n][3] = 0.0f;
        d1[n][0] = d1[n][1] = d1[n][2] = d1[n][3] = 0.0f;
    }
    const uint32_t* A0 = W0su + (mg * 32 + g) * WPITCH;        // tile0 row g
    const uint32_t* A1 = A0 + 8 * WPITCH;                      // tile0 row g+8
    const uint32_t* A2 = A0 + 16 * WPITCH;                     // tile1 row g
    const uint32_t* A3 = A0 + 24 * WPITCH;                     // tile1 row g+8

#define L1_KSTEP(k0)                                                              \
    {                                                                             \
        const uint32_t a00 = A0[(k0) + r], a01 = A1[(k0) + r];                    \
        const uint32_t a02 = A0[(k0) + r + 4], a03 = A1[(k0) + r + 4];            \
        const uint32_t a10 = A2[(k0) + r], a11 = A3[(k0) + r];                    \
        const uint32_t a12 = A2[(k0) + r + 4], a13 = A3[(k0) + r + 4];            \
        const uint32_t* Bk0 = Xsu + ((k0) + r) * XPITCH + nq * 32 + g;            \
        const uint32_t* Bk1 = Bk0 + 4 * XPITCH;                                   \
        _Pragma("unroll")                                                         \
        for (int n = 0; n < 4; n++) {                                             \
            const uint32_t b0v = Bk0[n * 8], b1v = Bk1[n * 8];                    \
            mma8(d0[n], a00, a01, a02, a03, b0v, b1v);                            \
            mma8(d1[n], a10, a11, a12, a13, b0v, b1v);                            \
        }                                                                         \
    }

#pragma unroll
    for (int k0 = 0; k0 < 64; k0 += 8) L1_KSTEP(k0);
    CP_WAIT(0);                 // X high half + weights landed
    __syncthreads();
#pragma unroll
    for (int k0 = 64; k0 < 128; k0 += 8) L1_KSTEP(k0);
#undef L1_KSTEP
    __syncthreads();            // all Xs reads done -> a1s (alias) writable

    // bias + ELU + scatter a1 (raw f32)
    {
        const int row0 = mg * 32 + g;
        const float bzA = sB0[row0],      bzB = sB0[row0 + 8];
        const float bzC = sB0[row0 + 16], bzD = sB0[row0 + 24];
#pragma unroll
        for (int n = 0; n < 4; n++) {
            const int px = nq * 32 + n * 8 + 2 * r;
            *(float2*)(a1s + row0 * XPITCH + px)        = make_float2(eluf(d0[n][0] + bzA), eluf(d0[n][1] + bzA));
            *(float2*)(a1s + (row0 + 8) * XPITCH + px)  = make_float2(eluf(d0[n][2] + bzB), eluf(d0[n][3] + bzB));
            *(float2*)(a1s + (row0 + 16) * XPITCH + px) = make_float2(eluf(d1[n][0] + bzC), eluf(d1[n][1] + bzC));
            *(float2*)(a1s + (row0 + 24) * XPITCH + px) = make_float2(eluf(d1[n][2] + bzD), eluf(d1[n][3] + bzD));
        }
    }
    __syncthreads();

    // ============ layer 2 MMA: D[32][128] = W1 x a1 ===============================
    {
        const int rb = wid & 1;       // row band (16 of 32 outs)
        const int wq = wid >> 1;      // pixel quarter
        float d[4][4];
#pragma unroll
        for (int n = 0; n < 4; n++) { d[n][0] = d[n][1] = d[n][2] = d[n][3] = 0.0f; }
        const uint32_t* W1r0 = W1su + (rb * 16 + g) * W1P;
        const uint32_t* W1r1 = W1r0 + 8 * W1P;
        const uint32_t* a1u  = (const uint32_t*)a1s;
#pragma unroll
        for (int k0 = 0; k0 < 64; k0 += 8) {
            const uint32_t a0 = W1r0[k0 + r];
            const uint32_t a1 = W1r1[k0 + r];
            const uint32_t a2 = W1r0[k0 + r + 4];
            const uint32_t a3 = W1r1[k0 + r + 4];
            const uint32_t* Bk0 = a1u + (k0 + r) * XPITCH + wq * 32 + g;
            const uint32_t* Bk1 = Bk0 + 4 * XPITCH;
#pragma unroll
            for (int n = 0; n < 4; n++) mma8(d[n], a0, a1, a2, a3, Bk0[n * 8], Bk1[n * 8]);
        }
        // a2s disjoint from a1s -> no barrier needed before scatter
        const int row0 = rb * 16 + g;
        const float bz0 = sB1[row0];
        const float bz1 = sB1[row0 + 8];
#pragma unroll
        for (int n = 0; n < 4; n++) {
            const int px = wq * 32 + n * 8 + 2 * r;
            *(float2*)(a2s + row0 * XPITCH + px)       = make_float2(eluf(d[n][0] + bz0), eluf(d[n][1] + bz0));
            *(float2*)(a2s + (row0 + 8) * XPITCH + px) = make_float2(eluf(d[n][2] + bz1), eluf(d[n][3] + bz1));
        }
    }
    __syncthreads();

    // ============ layer 3 MMA: D[16][128] = W2 x a2 (A preloaded in regs) =========
    {
        float d[2][4];
#pragma unroll
        for (int n = 0; n < 2; n++) { d[n][0] = d[n][1] = d[n][2] = d[n][3] = 0.0f; }
        const uint32_t* a2u = (const uint32_t*)a2s;
#pragma unroll
        for (int k0 = 0; k0 < 32; k0 += 8) {
            const int q = k0 >> 3;
            const uint32_t* Bk0 = a2u + (k0 + r) * XPITCH + wid * 16 + g;
            const uint32_t* Bk1 = Bk0 + 4 * XPITCH;
#pragma unroll
            for (int n = 0; n < 2; n++)
                mma8(d[n], a3f[q * 4 + 0], a3f[q * 4 + 1], a3f[q * 4 + 2], a3f[q * 4 + 3],
                     Bk0[n * 8], Bk1[n * 8]);
        }
        const float bz0 = sB2[g];
        const float bz1 = sB2[g + 8];
#pragma unroll
        for (int n = 0; n < 2; n++) {
            const int px = wid * 16 + n * 8 + 2 * r;
            *(float2*)(a3s + g * A3P + px)       = make_float2(eluf(d[n][0] + bz0), eluf(d[n][1] + bz0));
            *(float2*)(a3s + (g + 8) * A3P + px) = make_float2(eluf(d[n][2] + bz1), eluf(d[n][3] + bz1));
        }
    }
    __syncthreads();

    // ---- tail: layers 4-6 per pixel (t < 128) -> plane params --------------------
    if (t < P) {
        float a3[16];
#pragma unroll
        for (int c = 0; c < 16; c++) a3[c] = a3s[c * A3P + t];

        float a4[8];
        {
            const u64* b3p = (const u64*)sB3;
            u64 acc4[4];
#pragma unroll
            for (int j = 0; j < 4; j++) acc4[j] = b3p[j];
#pragma unroll
            for (int c = 0; c < 16; c++) {
                const u64 xx = pack2(a3[c], a3[c]);
                const ulonglong2 wa = *(const ulonglong2*)(wT3 + c * 8);
                const ulonglong2 wb = *(const ulonglong2*)(wT3 + c * 8 + 4);
                acc4[0] = fma2(wa.x, xx, acc4[0]); acc4[1] = fma2(wa.y, xx, acc4[1]);
                acc4[2] = fma2(wb.x, xx, acc4[2]); acc4[3] = fma2(wb.y, xx, acc4[3]);
            }
#pragma unroll
            for (int j = 0; j < 4; j++) {
                float lo, hi; unpack2(acc4[j], lo, hi);
                a4[2 * j] = eluf(lo); a4[2 * j + 1] = eluf(hi);
            }
        }
        float a5[4];
        {
            const u64* b4p = (const u64*)sB4;
            u64 acc5[2];
            acc5[0] = b4p[0]; acc5[1] = b4p[1];
#pragma unroll
            for (int c = 0; c < 8; c++) {
                const u64 xx = pack2(a4[c], a4[c]);
                const ulonglong2 w = *(const ulonglong2*)(wT4 + c * 4);
                acc5[0] = fma2(w.x, xx, acc5[0]); acc5[1] = fma2(w.y, xx, acc5[1]);
            }
            unpack2(acc5[0], a5[0], a5[1]); unpack2(acc5[1], a5[2], a5[3]);
        }
        float y[3];
#pragma unroll
        for (int o = 0; o < 3; o++) {
            float s = sBc[o];
#pragma unroll
            for (int c = 0; c < 4; c++) s += sWc[c * 3 + o] * a5[c];
            y[o] = s;
        }
        const float theta = sigmoidf_fast(y[0]) * (PI_F / 6.0f);
        const float phi   = sigmoidf_fast(y[1]) * (PI_F * 2.0f);
        const float dist  = sigmoidf_fast(y[2]) * MAX_DEPTH;
        const float st = __sinf(theta), ct = __cosf(theta);
        const float sp = __sinf(phi),   cp = __cosf(phi);
        float nx = st * cp, ny = st * sp, nz = ct;
        const float inv = rsqrtf(nx * nx + ny * ny + nz * nz);
        pln[0 * 128 + t] = nx * inv;
        pln[1 * 128 + t] = ny * inv;
        pln[2 * 128 + t] = nz * inv;
        pln[3 * 128 + t] = dist;
    }
    __syncthreads();

    // ---- epilogue: 2 threads per pixel, 4 rows each -------------------------------
    {
        const int px   = t >> 1;
        const int half = t & 1;
        const float nx   = pln[0 * 128 + px];
        const float ny   = pln[1 * 128 + px];
        const float nz   = pln[2 * 128 + px];
        const float dist = pln[3 * 128 + px];

        const int p  = p0 + px;
        const int bb = p / HWLO;
        const int hw = p - bb * HWLO;
        const int h  = hw / W8;
        const int w  = hw - h * W8;
        float* __restrict__ op = out + ((size_t)bb * HOUT + (size_t)h * 8) * WOUT + (size_t)w * 8;

#pragma unroll
        for (int rr = 0; rr < 4; rr++) {
            const int i = half * 4 + rr;
            const float vterm = ny * ((float)i - 3.5f) * 0.125f + nz;
            float row[8];
#pragma unroll
            for (int j = 0; j < 8; j++) {
                const float u = ((float)j - 3.5f) * 0.125f;
                row[j] = __fdividef(dist, nx * u + vterm);
            }
            float4* o4 = (float4*)(op + (size_t)i * WOUT);
            o4[0] = make_float4(row[0], row[1], row[2], row[3]);
            o4[1] = make_float4(row[4], row[5], row[6], row[7]);
        }
    }
}

extern "C" void kernel_launch(void* const* d_in, const int* in_sizes, int n_in,
                              void* d_out, int out_size) {
    const float* x  = (const float*)d_in[0];
    const float* w0 = (const float*)d_in[1];
    const float* b0 = (const float*)d_in[2];
    const float* w1 = (const float*)d_in[3];
    const float* b1 = (const float*)d_in[4];
    const float* w2 = (const float*)d_in[5];
    const float* b2 = (const float*)d_in[6];
    const float* w3 = (const float*)d_in[7];
    const float* b3 = (const float*)d_in[8];
    const float* w4 = (const float*)d_in[9];
    const float* b4 = (const float*)d_in[10];
    const float* wc = (const float*)d_in[11];
    const float* bc = (const float*)d_in[12];
    float* out = (float*)d_out;

    cudaFuncSetAttribute(lpg_mma_kernel,
                         cudaFuncAttributeMaxDynamicSharedMemorySize, SMEM_BYTES);

    lpg_mma_kernel<<<NTILES, NTHR, SMEM_BYTES>>>(x, w0, b0, w1, b1, w2, b2,
                                                 w3, b3, w4, b4, wc, bc, out);
}

// round 13
// speedup vs baseline: 3.6905x; 1.1156x over previous
#include <cuda_runtime.h>
#include <math.h>
#include <stdint.h>

#define NB    16
#define H8    44
#define W8    144
#define HWLO  (H8 * W8)        // 6336
#define NPIX  (NB * HWLO)      // 101376
#define HOUT  (H8 * 8)         // 352
#define WOUT  (W8 * 8)         // 1152
#define P     128              // pixels per tile
#define NTILES (NPIX / P)      // 792
#define NTHR  256
#define PI_F  3.1415926535f
#define MAX_DEPTH 81.0f

typedef unsigned long long u64;

#define XPITCH 136             // X f16-pair words / a1s f32 pitch (conflict-free)
#define W0P    68              // W0 f16-pair pitch (4g+r bijective)
#define W1P    68              // W1 f32 pitch
#define A3P    132             // a3s pitch

// ---- smem layout (float offsets) — aggressive aliasing ----
#define OFF_XS    0            // X f16x2 [64 pair][136] u32 = 8704
#define OFF_A1S   0            // alias: a1 f32 [64][136] = 8704 (X dead after L1)
#define OFF_PLN   0            // alias: [4][128] = 512 (a1 dead after L2)
#define OFF_W0S   8704         // W0 f16x2 [64][68] u32 = 4352
#define OFF_A2S   8704         // alias: a2 f32 [32][136] = 4352 (W0 dead after L1)
#define OFF_W1S   13056        // W1 f32 [32][68] = 2176
#define OFF_A3S   13056        // alias: a3 f32 [16][132] = 2112 (W1 dead after L2)
#define OFF_WT3   15232        // 128
#define OFF_WT4   15360        // 32
#define OFF_WC    15392        // 16
#define OFF_B0    15408        // 64
#define OFF_B1    15472        // 32
#define OFF_B2    15504        // 16
#define OFF_B3    15520        // 8
#define OFF_B4    15528        // 4
#define OFF_BC    15532        // 4
#define SMEM_FLOATS 15536
#define SMEM_BYTES  (SMEM_FLOATS * 4)   // 62144 B -> 3 CTAs/SM

// ---------------- helpers -------------------------------------------------------
__device__ __forceinline__ uint32_t smem_u32(const void* p) {
    uint32_t a;
    asm("{ .reg .u64 t; cvta.to.shared.u64 t, %1; cvt.u32.u64 %0, t; }" : "=r"(a) : "l"(p));
    return a;
}
__device__ __forceinline__ void cp_async16(uint32_t dst, const void* src) {
    asm volatile("cp.async.cg.shared.global [%0], [%1], 16;" :: "r"(dst), "l"(src));
}
#define CP_COMMIT() asm volatile("cp.async.commit_group;" ::: "memory")
#define CP_WAIT(N)  asm volatile("cp.async.wait_group %0;" :: "n"(N) : "memory")

// pack two f32 -> f16x2 (lo = first k element)
__device__ __forceinline__ uint32_t h2(float lo, float hi) {
    uint32_t r; asm("cvt.rn.f16x2.f32 %0, %1, %2;" : "=r"(r) : "f"(hi), "f"(lo)); return r;
}
__device__ __forceinline__ u64 pack2(float lo, float hi) {
    u64 r; asm("mov.b64 %0, {%1, %2};" : "=l"(r) : "f"(lo), "f"(hi)); return r;
}
__device__ __forceinline__ void unpack2(u64 v, float& lo, float& hi) {
    asm("mov.b64 {%0, %1}, %2;" : "=f"(lo), "=f"(hi) : "l"(v));
}
__device__ __forceinline__ u64 fma2(u64 a, u64 b, u64 c) {
    u64 d; asm("fma.rn.f32x2 %0, %1, %2, %3;" : "=l"(d) : "l"(a), "l"(b), "l"(c));
    return d;
}
__device__ __forceinline__ float eluf(float v) {
    return fmaxf(v, 0.0f) + (__expf(fminf(v, 0.0f)) - 1.0f);
}
__device__ __forceinline__ float sigmoidf_fast(float v) {
    return __fdividef(1.0f, 1.0f + __expf(-v));
}
// f16 m16n8k16: D += A x B (A row-major 16x16 f16x2, B col-major 16x8, fp32 acc)
__device__ __forceinline__ void mma16f(float* d, uint32_t a0, uint32_t a1, uint32_t a2,
                                       uint32_t a3, uint32_t b0, uint32_t b1) {
    asm volatile(
        "mma.sync.aligned.m16n8k16.row.col.f32.f16.f16.f32 "
        "{%0,%1,%2,%3}, {%4,%5,%6,%7}, {%8,%9}, {%0,%1,%2,%3};"
        : "+f"(d[0]), "+f"(d[1]), "+f"(d[2]), "+f"(d[3])
        : "r"(a0), "r"(a1), "r"(a2), "r"(a3), "r"(b0), "r"(b1));
}
// tf32 m16n8k8 (raw f32 bits -> HW truncates to tf32)
__device__ __forceinline__ void mma8(float* d, uint32_t a0, uint32_t a1, uint32_t a2,
                                     uint32_t a3, uint32_t b0, uint32_t b1) {
    asm volatile(
        "mma.sync.aligned.m16n8k8.row.col.f32.tf32.tf32.f32 "
        "{%0,%1,%2,%3}, {%4,%5,%6,%7}, {%8,%9}, {%0,%1,%2,%3};"
        : "+f"(d[0]), "+f"(d[1]), "+f"(d[2]), "+f"(d[3])
        : "r"(a0), "r"(a1), "r"(a2), "r"(a3), "r"(b0), "r"(b1));
}

// ---------------------------------- kernel ------------------------------------
__global__ __launch_bounds__(NTHR, 3) void lpg_mma_kernel(
    const float* __restrict__ x,
    const float* __restrict__ w0, const float* __restrict__ b0,
    const float* __restrict__ w1, const float* __restrict__ b1,
    const float* __restrict__ w2, const float* __restrict__ b2,
    const float* __restrict__ w3, const float* __restrict__ b3,
    const float* __restrict__ w4, const float* __restrict__ b4,
    const float* __restrict__ wc, const float* __restrict__ bc,
    float* __restrict__ out)
{
    extern __shared__ float sm[];
    uint32_t* Xsu  = (uint32_t*)(sm + OFF_XS);    // f16x2 channel pairs
    uint32_t* W0su = (uint32_t*)(sm + OFF_W0S);
    float*    a1s = sm + OFF_A1S;
    float*    a2s = sm + OFF_A2S;
    float*    a3s = sm + OFF_A3S;
    float*    pln = sm + OFF_PLN;
    const uint32_t* W1su = (const uint32_t*)(sm + OFF_W1S);
    float* wT3 = sm + OFF_WT3;
    float* wT4 = sm + OFF_WT4;
    float* sWc = sm + OFF_WC;
    float* sB0 = sm + OFF_B0;
    float* sB1 = sm + OFF_B1;
    float* sB2 = sm + OFF_B2;
    float* sB3 = sm + OFF_B3;
    float* sB4 = sm + OFF_B4;
    float* sBc = sm + OFF_BC;

    const int t   = threadIdx.x;
    const int wid = t >> 5;
    const int lid = t & 31;
    const int p0  = blockIdx.x * P;
    const int g   = lid >> 2;      // MMA groupID
    const int r   = lid & 3;       // MMA threadID-in-group

    const uint32_t sbase = smem_u32(sm);

    // ---- W1 via cp.async (raw f32, flows while we convert X/W0) -------------------
#pragma unroll
    for (int i = 0; i < 2; i++) {
        const int j = t + i * 256;            // 0..511 float4
        const int o = j >> 4, cq = j & 15;
        cp_async16(sbase + (uint32_t)((OFF_W1S + o * W1P + cq * 4) * 4),
                   w1 + o * 64 + cq * 4);
    }
    CP_COMMIT();

    // ---- stage X [128ch][128px] -> f16x2 channel-pairs [64][136] -------------------
    {
        const int q4 = t & 31;                // uint4 (= 4 pixels) index
        const int p  = p0 + 4 * q4;
        const int bb = p / HWLO;
        const int hw = p - bb * HWLO;
        const float* __restrict__ xb = x + ((size_t)bb * 128) * HWLO + hw;
        const int cp0 = t >> 5;               // pair-row base
#pragma unroll
        for (int i = 0; i < 8; i++) {
            const int cpair = cp0 + i * 8;    // 0..63
            const float4 v0 = __ldg((const float4*)(xb + (size_t)(2 * cpair) * HWLO));
            const float4 v1 = __ldg((const float4*)(xb + (size_t)(2 * cpair + 1) * HWLO));
            uint4 u;
            u.x = h2(v0.x, v1.x); u.y = h2(v0.y, v1.y);
            u.z = h2(v0.z, v1.z); u.w = h2(v0.w, v1.w);
            *(uint4*)(Xsu + cpair * XPITCH + 4 * q4) = u;
        }
    }
    // ---- stage W0 [64][128] -> f16x2 k-pairs [64][68] -------------------------------
#pragma unroll
    for (int i = 0; i < 4; i++) {
        const int j = t + i * 256;            // 0..1023
        const int o = j >> 4, q = j & 15;     // row, 4-pair block
        const float4 va = __ldg((const float4*)(w0 + o * 128 + 8 * q));
        const float4 vb = __ldg((const float4*)(w0 + o * 128 + 8 * q + 4));
        uint4 u;
        u.x = h2(va.x, va.y); u.y = h2(va.z, va.w);
        u.z = h2(vb.x, vb.y); u.w = h2(vb.z, vb.w);
        *(uint4*)(W0su + o * W0P + 4 * q) = u;
    }
    // ---- small staging ---------------------------------------------------------------
    if (t < 128) { int o = t >> 4, c = t & 15; wT3[c * 8 + o] = w3[t]; }
    if (t < 32)  { int o = t >> 3, c = t & 7;  wT4[c * 4 + o] = w4[t]; }
    if (t < 12)  { int o = t >> 2, c = t & 3;  sWc[c * 3 + o] = wc[t]; }
    if (t < 64) sB0[t] = b0[t];
    if (t < 32) sB1[t] = b1[t];
    if (t < 16) sB2[t] = b2[t];
    if (t < 8)  sB3[t] = b3[t];
    if (t < 4)  sB4[t] = b4[t];
    if (t < 3)  sBc[t] = bc[t];

    CP_WAIT(0);
    __syncthreads();

    // ============ layer 1 MMA (f16 k16): D[64][128] = W0 x X =======================
    const int mg = wid & 1;        // m-half
    const int nq = wid >> 1;       // pixel quarter
    float d0[4][4], d1[4][4];
#pragma unroll
    for (int n = 0; n < 4; n++) {
        d0[n][0] = d0[n][1] = d0[n][2] = d0[n][3] = 0.0f;
        d1[n][0] = d1[n][1] = d1[n][2] = d1[n][3] = 0.0f;
    }
    {
        const int row0 = mg * 32 + g;
        const uint32_t* A0 = W0su + row0 * W0P;
        const uint32_t* A1 = A0 + 8 * W0P;
        const uint32_t* A2 = A0 + 16 * W0P;
        const uint32_t* A3 = A0 + 24 * W0P;
#pragma unroll
        for (int kb = 0; kb < 8; kb++) {
            const int kp = kb * 8;            // pair-row base (16 channels)
            const uint32_t a00 = A0[kp + r],     a01 = A1[kp + r];
            const uint32_t a02 = A0[kp + r + 4], a03 = A1[kp + r + 4];
            const uint32_t a10 = A2[kp + r],     a11 = A3[kp + r];
            const uint32_t a12 = A2[kp + r + 4], a13 = A3[kp + r + 4];
            const uint32_t* Bk0 = Xsu + (kp + r) * XPITCH + nq * 32 + g;
            const uint32_t* Bk1 = Bk0 + 4 * XPITCH;
#pragma unroll
            for (int n = 0; n < 4; n++) {
                const uint32_t b0v = Bk0[n * 8], b1v = Bk1[n * 8];
                mma16f(d0[n], a00, a01, a02, a03, b0v, b1v);
                mma16f(d1[n], a10, a11, a12, a13, b0v, b1v);
            }
        }
    }
    __syncthreads();            // all X/W0 reads done -> a1s (alias) writable

    // bias + ELU + scatter a1 (f32)
    {
        const int row0 = mg * 32 + g;
        const float bzA = sB0[row0],      bzB = sB0[row0 + 8];
        const float bzC = sB0[row0 + 16], bzD = sB0[row0 + 24];
#pragma unroll
        for (int n = 0; n < 4; n++) {
            const int px = nq * 32 + n * 8 + 2 * r;
            *(float2*)(a1s + row0 * XPITCH + px)        = make_float2(eluf(d0[n][0] + bzA), eluf(d0[n][1] + bzA));
            *(float2*)(a1s + (row0 + 8) * XPITCH + px)  = make_float2(eluf(d0[n][2] + bzB), eluf(d0[n][3] + bzB));
            *(float2*)(a1s + (row0 + 16) * XPITCH + px) = make_float2(eluf(d1[n][0] + bzC), eluf(d1[n][1] + bzC));
            *(float2*)(a1s + (row0 + 24) * XPITCH + px) = make_float2(eluf(d1[n][2] + bzD), eluf(d1[n][3] + bzD));
        }
    }
    __syncthreads();

    // ============ layer 2 MMA (tf32): D[32][128] = W1 x a1 ==========================
    {
        const int rb = wid & 1;
        const int wq = wid >> 1;
        float d[4][4];
#pragma unroll
        for (int n = 0; n < 4; n++) { d[n][0] = d[n][1] = d[n][2] = d[n][3] = 0.0f; }
        const uint32_t* W1r0 = W1su + (rb * 16 + g) * W1P;
        const uint32_t* W1r1 = W1r0 + 8 * W1P;
        const uint32_t* a1u  = (const uint32_t*)a1s;
#pragma unroll
        for (int k0 = 0; k0 < 64; k0 += 8) {
            const uint32_t a0 = W1r0[k0 + r];
            const uint32_t a1 = W1r1[k0 + r];
            const uint32_t a2 = W1r0[k0 + r + 4];
            const uint32_t a3 = W1r1[k0 + r + 4];
            const uint32_t* Bk0 = a1u + (k0 + r) * XPITCH + wq * 32 + g;
            const uint32_t* Bk1 = Bk0 + 4 * XPITCH;
#pragma unroll
            for (int n = 0; n < 4; n++) mma8(d[n], a0, a1, a2, a3, Bk0[n * 8], Bk1[n * 8]);
        }
        __syncthreads();        // W1 reads done before... (a2s aliases W0, already dead;
                                // keep barrier so all a1 reads precede nothing hazardous —
                                // actually needed: a2s writes must not race other warps'
                                // layer-2 B reads? a2s (OFF 8704) disjoint from a1s (0..8704) ✓
                                // barrier here orders W1-region reads before layer-3 a3s writes.
        const int row0 = rb * 16 + g;
        const float bz0 = sB1[row0];
        const float bz1 = sB1[row0 + 8];
#pragma unroll
        for (int n = 0; n < 4; n++) {
            const int px = wq * 32 + n * 8 + 2 * r;
            *(float2*)(a2s + row0 * XPITCH + px)       = make_float2(eluf(d[n][0] + bz0), eluf(d[n][1] + bz0));
            *(float2*)(a2s + (row0 + 8) * XPITCH + px) = make_float2(eluf(d[n][2] + bz1), eluf(d[n][3] + bz1));
        }
    }
    __syncthreads();

    // ============ layer 3 MMA (tf32): D[16][128] = W2 x a2 (A from global) ==========
    {
        uint32_t a3f[16];
#pragma unroll
        for (int k0 = 0; k0 < 32; k0 += 8) {
            const int q = k0 >> 3;
            a3f[q * 4 + 0] = __float_as_uint(__ldg(w2 + g * 32 + k0 + r));
            a3f[q * 4 + 1] = __float_as_uint(__ldg(w2 + (g + 8) * 32 + k0 + r));
            a3f[q * 4 + 2] = __float_as_uint(__ldg(w2 + g * 32 + k0 + r + 4));
            a3f[q * 4 + 3] = __float_as_uint(__ldg(w2 + (g + 8) * 32 + k0 + r + 4));
        }
        float d[2][4];
#pragma unroll
        for (int n = 0; n < 2; n++) { d[n][0] = d[n][1] = d[n][2] = d[n][3] = 0.0f; }
        const uint32_t* a2u = (const uint32_t*)a2s;
#pragma unroll
        for (int k0 = 0; k0 < 32; k0 += 8) {
            const int q = k0 >> 3;
            const uint32_t* Bk0 = a2u + (k0 + r) * XPITCH + wid * 16 + g;
            const uint32_t* Bk1 = Bk0 + 4 * XPITCH;
#pragma unroll
            for (int n = 0; n < 2; n++)
                mma8(d[n], a3f[q * 4 + 0], a3f[q * 4 + 1], a3f[q * 4 + 2], a3f[q * 4 + 3],
                     Bk0[n * 8], Bk1[n * 8]);
        }
        const float bz0 = sB2[g];
        const float bz1 = sB2[g + 8];
#pragma unroll
        for (int n = 0; n < 2; n++) {
            const int px = wid * 16 + n * 8 + 2 * r;
            *(float2*)(a3s + g * A3P + px)       = make_float2(eluf(d[n][0] + bz0), eluf(d[n][1] + bz0));
            *(float2*)(a3s + (g + 8) * A3P + px) = make_float2(eluf(d[n][2] + bz1), eluf(d[n][3] + bz1));
        }
    }
    __syncthreads();

    // ---- tail: layers 4-6 per pixel (t < 128) -> plane params ----------------------
    if (t < P) {
        float a3[16];
#pragma unroll
        for (int c = 0; c < 16; c++) a3[c] = a3s[c * A3P + t];

        float a4[8];
        {
            const u64* b3p = (const u64*)sB3;
            u64 acc4[4];
#pragma unroll
            for (int j = 0; j < 4; j++) acc4[j] = b3p[j];
#pragma unroll
            for (int c = 0; c < 16; c++) {
                const u64 xx = pack2(a3[c], a3[c]);
                const ulonglong2 wa = *(const ulonglong2*)(wT3 + c * 8);
                const ulonglong2 wb = *(const ulonglong2*)(wT3 + c * 8 + 4);
                acc4[0] = fma2(wa.x, xx, acc4[0]); acc4[1] = fma2(wa.y, xx, acc4[1]);
                acc4[2] = fma2(wb.x, xx, acc4[2]); acc4[3] = fma2(wb.y, xx, acc4[3]);
            }
#pragma unroll
            for (int j = 0; j < 4; j++) {
                float lo, hi; unpack2(acc4[j], lo, hi);
                a4[2 * j] = eluf(lo); a4[2 * j + 1] = eluf(hi);
            }
        }
        float a5[4];
        {
            const u64* b4p = (const u64*)sB4;
            u64 acc5[2];
            acc5[0] = b4p[0]; acc5[1] = b4p[1];
#pragma unroll
            for (int c = 0; c < 8; c++) {
                const u64 xx = pack2(a4[c], a4[c]);
                const ulonglong2 w = *(const ulonglong2*)(wT4 + c * 4);
                acc5[0] = fma2(w.x, xx, acc5[0]); acc5[1] = fma2(w.y, xx, acc5[1]);
            }
            unpack2(acc5[0], a5[0], a5[1]); unpack2(acc5[1], a5[2], a5[3]);
        }
        float y[3];
#pragma unroll
        for (int o = 0; o < 3; o++) {
            float s = sBc[o];
#pragma unroll
            for (int c = 0; c < 4; c++) s += sWc[c * 3 + o] * a5[c];
            y[o] = s;
        }
        const float theta = sigmoidf_fast(y[0]) * (PI_F / 6.0f);
        const float phi   = sigmoidf_fast(y[1]) * (PI_F * 2.0f);
        const float dist  = sigmoidf_fast(y[2]) * MAX_DEPTH;
        const float st = __sinf(theta), ct = __cosf(theta);
        const float sp = __sinf(phi),   cp = __cosf(phi);
        float nx = st * cp, ny = st * sp, nz = ct;
        const float inv = rsqrtf(nx * nx + ny * ny + nz * nz);
        pln[0 * 128 + t] = nx * inv;
        pln[1 * 128 + t] = ny * inv;
        pln[2 * 128 + t] = nz * inv;
        pln[3 * 128 + t] = dist;
    }
    __syncthreads();

    // ---- epilogue: 2 threads per pixel, 4 rows each ---------------------------------
    {
        const int px   = t >> 1;
        const int half = t & 1;
        const float nx   = pln[0 * 128 + px];
        const float ny   = pln[1 * 128 + px];
        const float nz   = pln[2 * 128 + px];
        const float dist = pln[3 * 128 + px];

        const int p  = p0 + px;
        const int bb = p / HWLO;
        const int hw = p - bb * HWLO;
        const int h  = hw / W8;
        const int w  = hw - h * W8;
        float* __restrict__ op = out + ((size_t)bb * HOUT + (size_t)h * 8) * WOUT + (size_t)w * 8;

#pragma unroll
        for (int rr = 0; rr < 4; rr++) {
            const int i = half * 4 + rr;
            const float vterm = ny * ((float)i - 3.5f) * 0.125f + nz;
            float row[8];
#pragma unroll
            for (int j = 0; j < 8; j++) {
                const float u = ((float)j - 3.5f) * 0.125f;
                row[j] = __fdividef(dist, nx * u + vterm);
            }
            float4* o4 = (float4*)(op + (size_t)i * WOUT);
            o4[0] = make_float4(row[0], row[1], row[2], row[3]);
            o4[1] = make_float4(row[4], row[5], row[6], row[7]);
        }
    }
}

extern "C" void kernel_launch(void* const* d_in, const int* in_sizes, int n_in,
                              void* d_out, int out_size) {
    const float* x  = (const float*)d_in[0];
    const float* w0 = (const float*)d_in[1];
    const float* b0 = (const float*)d_in[2];
    const float* w1 = (const float*)d_in[3];
    const float* b1 = (const float*)d_in[4];
    const float* w2 = (const float*)d_in[5];
    const float* b2 = (const float*)d_in[6];
    const float* w3 = (const float*)d_in[7];
    const float* b3 = (const float*)d_in[8];
    const float* w4 = (const float*)d_in[9];
    const float* b4 = (const float*)d_in[10];
    const float* wc = (const float*)d_in[11];
    const float* bc = (const float*)d_in[12];
    float* out = (float*)d_out;

    cudaFuncSetAttribute(lpg_mma_kernel,
                         cudaFuncAttributeMaxDynamicSharedMemorySize, SMEM_BYTES);

    lpg_mma_kernel<<<NTILES, NTHR, SMEM_BYTES>>>(x, w0, b0, w1, b1, w2, b2,
                                                 w3, b3, w4, b4, wc, bc, out);
}